// round 2
// baseline (speedup 1.0000x reference)
#include <cuda_runtime.h>
#include <cuda_fp16.h>
#include <cstdint>
#include <math.h>

// ---------------------------------------------------------------------------
// Problem constants
// ---------------------------------------------------------------------------
#define HIMG   56
#define WSZ    7
#define SSZ    3
#define DIM    384
#define HEADS  12
#define HDIM   32
#define NBATCH 16
#define NTOK   (NBATCH * HIMG * HIMG)     // 50176 rows
#define NWIMG  64                          // windows per image (8x8)
#define NWIN   (NBATCH * NWIMG)            // 1024 windows
#define NT     49                          // tokens per window

// ---------------------------------------------------------------------------
// Static scratch (no allocations allowed)
// ---------------------------------------------------------------------------
__device__ __half g_Awin[(size_t)NTOK * DIM];       // LN1+shift+partition, fp16
__device__ float  g_Q[(size_t)NTOK * DIM];          // [win][head][n][d] fp32 (pre-scaled)
__device__ float  g_K[(size_t)NTOK * DIM];
__device__ float  g_V[(size_t)NTOK * DIM];
__device__ __half g_O[(size_t)NTOK * DIM];          // attention out, row = win*49+n
__device__ __half g_A2[(size_t)NTOK * DIM];         // LN2(y1) fp16
__device__ __half g_Hm[(size_t)NTOK * 4 * DIM];     // gelu(fc1) fp16
__device__ __half g_Wqkv[DIM * 3 * DIM];
__device__ __half g_Wproj[DIM * DIM];
__device__ __half g_Wfc1[DIM * 4 * DIM];
__device__ __half g_Wfc2[4 * DIM * DIM];

// ---------------------------------------------------------------------------
// fp32 -> fp16 weight conversion
// ---------------------------------------------------------------------------
__global__ void f2h_kernel(const float* __restrict__ s, __half* __restrict__ d, int n) {
    int i = blockIdx.x * blockDim.x + threadIdx.x;
    if (i < n) d[i] = __float2half(s[i]);
}

// ---------------------------------------------------------------------------
// LayerNorm (+ optional shift/window gather). One warp per row.
// ---------------------------------------------------------------------------
__device__ __forceinline__ float warp_sum(float v) {
#pragma unroll
    for (int o = 16; o > 0; o >>= 1) v += __shfl_xor_sync(0xFFFFFFFFu, v, o);
    return v;
}

// gather variant: row r is a window-token; source token via +3 cyclic shift
__global__ void ln_gather_kernel(const float* __restrict__ x,
                                 const float* __restrict__ g,
                                 const float* __restrict__ b,
                                 __half* __restrict__ out) {
    int r    = blockIdx.x * 4 + (threadIdx.x >> 5);
    int lane = threadIdx.x & 31;
    int w = r / NT, n = r - w * NT;
    int bimg = w >> 6, wi = w & 63;
    int wr = wi >> 3, wc = wi & 7;
    int i = n / WSZ, j = n - i * WSZ;
    int hh = wr * WSZ + i + SSZ; if (hh >= HIMG) hh -= HIMG;
    int ww = wc * WSZ + j + SSZ; if (ww >= HIMG) ww -= HIMG;
    size_t t = (size_t)bimg * (HIMG * HIMG) + hh * HIMG + ww;

    const float* xp = x + t * DIM;
    float v[12];
    float s = 0.f;
#pragma unroll
    for (int k = 0; k < 12; k++) { v[k] = xp[lane + k * 32]; s += v[k]; }
    float mu = warp_sum(s) * (1.0f / DIM);
    float s2 = 0.f;
#pragma unroll
    for (int k = 0; k < 12; k++) { float d0 = v[k] - mu; s2 += d0 * d0; }
    float var = warp_sum(s2) * (1.0f / DIM);
    float rs = rsqrtf(var + 1e-5f);
    __half* op = out + (size_t)r * DIM;
#pragma unroll
    for (int k = 0; k < 12; k++) {
        int c = lane + k * 32;
        op[c] = __float2half((v[k] - mu) * rs * g[c] + b[c]);
    }
}

// plain variant (token order)
__global__ void ln_plain_kernel(const float* __restrict__ x,
                                const float* __restrict__ g,
                                const float* __restrict__ b,
                                __half* __restrict__ out) {
    int r    = blockIdx.x * 4 + (threadIdx.x >> 5);
    int lane = threadIdx.x & 31;
    const float* xp = x + (size_t)r * DIM;
    float v[12];
    float s = 0.f;
#pragma unroll
    for (int k = 0; k < 12; k++) { v[k] = xp[lane + k * 32]; s += v[k]; }
    float mu = warp_sum(s) * (1.0f / DIM);
    float s2 = 0.f;
#pragma unroll
    for (int k = 0; k < 12; k++) { float d0 = v[k] - mu; s2 += d0 * d0; }
    float var = warp_sum(s2) * (1.0f / DIM);
    float rs = rsqrtf(var + 1e-5f);
    __half* op = out + (size_t)r * DIM;
#pragma unroll
    for (int k = 0; k < 12; k++) {
        int c = lane + k * 32;
        op[c] = __float2half((v[k] - mu) * rs * g[c] + b[c]);
    }
}

// ---------------------------------------------------------------------------
// fp16 GEMM (mma.sync m16n8k16), 128x128x32 tiles, 8 warps, fused epilogue.
// A: [M,K] row-major fp16, B: [K,N] row-major fp16, C consumed by Epi(r,c,v).
// M % 128 == 0, N % 128 == 0, K % 32 == 0 (all hold for this problem).
// ---------------------------------------------------------------------------
__device__ __forceinline__ unsigned smem_u32(const void* p) {
    return (unsigned)__cvta_generic_to_shared(p);
}

template <class Epi>
__global__ void __launch_bounds__(256)
gemm_f16_kernel(const __half* __restrict__ A, const __half* __restrict__ Bw,
                int M, int N, int K, Epi epi) {
    constexpr int BM = 128, BN = 128, BK = 32;
    __shared__ __half Ash[BM][BK + 8];
    __shared__ __half Bsh[BK][BN + 8];

    const int tid = threadIdx.x;
    const int warp = tid >> 5, lane = tid & 31;
    const int wm = (warp >> 2) * 64;   // 2 warps along M
    const int wn = (warp & 3) * 32;    // 4 warps along N
    const int bm = blockIdx.y * BM;
    const int bn = blockIdx.x * BN;

    float acc[4][4][4];
#pragma unroll
    for (int a = 0; a < 4; a++)
#pragma unroll
        for (int b = 0; b < 4; b++)
#pragma unroll
            for (int c = 0; c < 4; c++) acc[a][b][c] = 0.f;

    for (int k0 = 0; k0 < K; k0 += BK) {
        // stage A tile (128 x 32 halves): 512 16B chunks
#pragma unroll
        for (int it = 0; it < 2; it++) {
            int idx = tid + it * 256;
            int r = idx >> 2, cc = (idx & 3) * 8;
            *(uint4*)&Ash[r][cc] =
                *(const uint4*)&A[(size_t)(bm + r) * K + k0 + cc];
        }
        // stage B tile (32 x 128 halves)
#pragma unroll
        for (int it = 0; it < 2; it++) {
            int idx = tid + it * 256;
            int r = idx >> 4, cc = (idx & 15) * 8;
            *(uint4*)&Bsh[r][cc] =
                *(const uint4*)&Bw[(size_t)(k0 + r) * N + bn + cc];
        }
        __syncthreads();

#pragma unroll
        for (int kk = 0; kk < BK; kk += 16) {
            uint32_t af[4][4], bf[4][2];
#pragma unroll
            for (int mi = 0; mi < 4; mi++) {
                unsigned addr = smem_u32(&Ash[wm + mi * 16 + (lane & 15)]
                                             [kk + (lane >> 4) * 8]);
                asm volatile(
                    "ldmatrix.sync.aligned.m8n8.x4.shared.b16 {%0,%1,%2,%3}, [%4];\n"
                    : "=r"(af[mi][0]), "=r"(af[mi][1]), "=r"(af[mi][2]), "=r"(af[mi][3])
                    : "r"(addr));
            }
#pragma unroll
            for (int ni = 0; ni < 4; ni++) {
                unsigned addr = smem_u32(&Bsh[kk + (lane & 15)][wn + ni * 8]);
                asm volatile(
                    "ldmatrix.sync.aligned.m8n8.x2.trans.shared.b16 {%0,%1}, [%2];\n"
                    : "=r"(bf[ni][0]), "=r"(bf[ni][1])
                    : "r"(addr));
            }
#pragma unroll
            for (int mi = 0; mi < 4; mi++)
#pragma unroll
                for (int ni = 0; ni < 4; ni++) {
                    asm volatile(
                        "mma.sync.aligned.m16n8k16.row.col.f32.f16.f16.f32 "
                        "{%0,%1,%2,%3}, {%4,%5,%6,%7}, {%8,%9}, {%0,%1,%2,%3};\n"
                        : "+f"(acc[mi][ni][0]), "+f"(acc[mi][ni][1]),
                          "+f"(acc[mi][ni][2]), "+f"(acc[mi][ni][3])
                        : "r"(af[mi][0]), "r"(af[mi][1]), "r"(af[mi][2]), "r"(af[mi][3]),
                          "r"(bf[ni][0]), "r"(bf[ni][1]));
                }
        }
        __syncthreads();
    }

    // epilogue: element (r,c) per mma fragment layout
    const int r0 = bm + wm + (lane >> 2);
    const int c0 = bn + wn + (lane & 3) * 2;
#pragma unroll
    for (int mi = 0; mi < 4; mi++) {
#pragma unroll
        for (int ni = 0; ni < 4; ni++) {
            int rr = r0 + mi * 16;
            int cc = c0 + ni * 8;
            epi(rr,     cc,     acc[mi][ni][0]);
            epi(rr,     cc + 1, acc[mi][ni][1]);
            epi(rr + 8, cc,     acc[mi][ni][2]);
            epi(rr + 8, cc + 1, acc[mi][ni][3]);
        }
    }
}

// ---------------------------------------------------------------------------
// Epilogue functors
// ---------------------------------------------------------------------------
struct EpiQKV {
    const float* bias;
    float scale;
    float *Qo, *Ko, *Vo;
    __device__ __forceinline__ void operator()(int r, int c, float v) const {
        v += bias[c];
        int which = c / DIM;
        int rem = c - which * DIM;
        int h = rem >> 5, d = rem & 31;
        int w = r / NT, n = r - w * NT;
        size_t dst = (((size_t)(w * HEADS + h)) * NT + n) * HDIM + d;
        if (which == 0)      Qo[dst] = v * scale;
        else if (which == 1) Ko[dst] = v;
        else                 Vo[dst] = v;
    }
};

struct EpiProj {  // + bias, window-reverse + unshift scatter, + x1 residual -> y1
    const float* bias;
    const float* x1;
    float* y1;
    __device__ __forceinline__ void operator()(int r, int c, float v) const {
        int w = r / NT, n = r - w * NT;
        int bimg = w >> 6, wi = w & 63;
        int wr = wi >> 3, wc = wi & 7;
        int i = n / WSZ, j = n - i * WSZ;
        int hh = wr * WSZ + i + SSZ; if (hh >= HIMG) hh -= HIMG;
        int ww = wc * WSZ + j + SSZ; if (ww >= HIMG) ww -= HIMG;
        size_t t = (size_t)bimg * (HIMG * HIMG) + hh * HIMG + ww;
        size_t o = t * DIM + c;
        y1[o] = x1[o] + v + bias[c];
    }
};

struct EpiGelu {  // + bias, exact gelu, fp16 store
    const float* bias;
    __half* Ho;
    __device__ __forceinline__ void operator()(int r, int c, float v) const {
        v += bias[c];
        float gl = 0.5f * v * (1.0f + erff(v * 0.70710678118654752f));
        Ho[(size_t)r * (4 * DIM) + c] = __float2half(gl);
    }
};

struct EpiY2 {  // + bias + x2 residual -> y2
    const float* bias;
    const float* x2;
    float* y2;
    __device__ __forceinline__ void operator()(int r, int c, float v) const {
        size_t o = (size_t)r * DIM + c;
        y2[o] = x2[o] + v + bias[c];
    }
};

// ---------------------------------------------------------------------------
// Windowed attention: one block per (window, head). fp32 softmax.
// Q pre-scaled by 1/sqrt(d). Output fp16 in proj-GEMM A layout.
// ---------------------------------------------------------------------------
__global__ void __launch_bounds__(64)
attn_kernel(const float* __restrict__ Q, const float* __restrict__ K,
            const float* __restrict__ V, const float* __restrict__ rpb,
            const float* __restrict__ mask, __half* __restrict__ O) {
    int wh = blockIdx.x;
    int w = wh / HEADS, h = wh - w * HEADS;
    int wi = w & 63;   // window index within image (for mask)

    __shared__ float ks[NT][HDIM];
    __shared__ float vs[NT][HDIM];

    const size_t base = (size_t)wh * NT * HDIM;
    for (int idx = threadIdx.x; idx < NT * HDIM; idx += 64) {
        ks[idx >> 5][idx & 31] = K[base + idx];
        vs[idx >> 5][idx & 31] = V[base + idx];
    }
    __syncthreads();

    int n = threadIdx.x;
    if (n < NT) {
        float q[HDIM];
        const float* qp = Q + base + (size_t)n * HDIM;
#pragma unroll
        for (int d = 0; d < HDIM; d++) q[d] = qp[d];

        int i1 = n / WSZ, j1 = n - i1 * WSZ;
        const float* mrow = mask + ((size_t)wi * NT + n) * NT;

        float s[NT];
        float mx = -1e30f;
#pragma unroll
        for (int m = 0; m < NT; m++) {
            float dot = 0.f;
#pragma unroll
            for (int d = 0; d < HDIM; d++) dot += q[d] * ks[m][d];
            int i2 = m / WSZ, j2 = m - i2 * WSZ;
            int ridx = (i1 - i2 + WSZ - 1) * (2 * WSZ - 1) + (j1 - j2 + WSZ - 1);
            float val = dot + rpb[ridx * HEADS + h] + mrow[m];
            s[m] = val;
            mx = fmaxf(mx, val);
        }
        float sum = 0.f;
#pragma unroll
        for (int m = 0; m < NT; m++) {
            float p = expf(s[m] - mx);
            s[m] = p;
            sum += p;
        }
        float inv = 1.0f / sum;

        float o[HDIM];
#pragma unroll
        for (int d = 0; d < HDIM; d++) o[d] = 0.f;
#pragma unroll
        for (int m = 0; m < NT; m++) {
            float p = s[m];
#pragma unroll
            for (int d = 0; d < HDIM; d++) o[d] += p * vs[m][d];
        }
        __half* op = O + ((size_t)(w * NT + n)) * DIM + h * HDIM;
#pragma unroll
        for (int d = 0; d < HDIM; d++) op[d] = __float2half(o[d] * inv);
    }
}

// ---------------------------------------------------------------------------
// Launch
// ---------------------------------------------------------------------------
extern "C" void kernel_launch(void* const* d_in, const int* in_sizes, int n_in,
                              void* d_out, int out_size) {
    const float* x1     = (const float*)d_in[0];
    const float* x2     = (const float*)d_in[1];
    const float* amask  = (const float*)d_in[2];
    const float* g1     = (const float*)d_in[3];
    const float* be1    = (const float*)d_in[4];
    const float* w_qkv  = (const float*)d_in[5];
    const float* b_qkv  = (const float*)d_in[6];
    const float* rpb    = (const float*)d_in[7];
    const float* w_proj = (const float*)d_in[8];
    const float* b_proj = (const float*)d_in[9];
    const float* g2     = (const float*)d_in[10];
    const float* be2    = (const float*)d_in[11];
    const float* w_fc1  = (const float*)d_in[12];
    const float* b_fc1  = (const float*)d_in[13];
    const float* w_fc2  = (const float*)d_in[14];
    const float* b_fc2  = (const float*)d_in[15];

    float* out = (float*)d_out;
    float* y1 = out;
    float* y2 = out + (size_t)NTOK * DIM;

    // symbol addresses (host-side, not captured — addresses are stable)
    void *pAwin, *pQ, *pK, *pV, *pO, *pA2, *pH;
    void *pWqkv, *pWproj, *pWfc1, *pWfc2;
    cudaGetSymbolAddress(&pAwin, g_Awin);
    cudaGetSymbolAddress(&pQ, g_Q);
    cudaGetSymbolAddress(&pK, g_K);
    cudaGetSymbolAddress(&pV, g_V);
    cudaGetSymbolAddress(&pO, g_O);
    cudaGetSymbolAddress(&pA2, g_A2);
    cudaGetSymbolAddress(&pH, g_Hm);
    cudaGetSymbolAddress(&pWqkv, g_Wqkv);
    cudaGetSymbolAddress(&pWproj, g_Wproj);
    cudaGetSymbolAddress(&pWfc1, g_Wfc1);
    cudaGetSymbolAddress(&pWfc2, g_Wfc2);

    // weights -> fp16
    f2h_kernel<<<(DIM * 3 * DIM + 255) / 256, 256>>>(w_qkv, (__half*)pWqkv, DIM * 3 * DIM);
    f2h_kernel<<<(DIM * DIM + 255) / 256, 256>>>(w_proj, (__half*)pWproj, DIM * DIM);
    f2h_kernel<<<(DIM * 4 * DIM + 255) / 256, 256>>>(w_fc1, (__half*)pWfc1, DIM * 4 * DIM);
    f2h_kernel<<<(4 * DIM * DIM + 255) / 256, 256>>>(w_fc2, (__half*)pWfc2, 4 * DIM * DIM);

    const int M = NTOK;

    // 1) LN1 + shift + window partition
    ln_gather_kernel<<<NTOK / 4, 128>>>(x2, g1, be1, (__half*)pAwin);

    // 2) QKV GEMM + scatter
    {
        EpiQKV e{b_qkv, 0.17677669529663687f, (float*)pQ, (float*)pK, (float*)pV};
        gemm_f16_kernel<EpiQKV><<<dim3(3 * DIM / 128, M / 128), 256>>>(
            (const __half*)pAwin, (const __half*)pWqkv, M, 3 * DIM, DIM, e);
    }

    // 3) attention
    attn_kernel<<<NWIN * HEADS, 64>>>((const float*)pQ, (const float*)pK,
                                      (const float*)pV, rpb, amask, (__half*)pO);

    // 4) proj + window reverse + residual -> y1
    {
        EpiProj e{b_proj, x1, y1};
        gemm_f16_kernel<EpiProj><<<dim3(DIM / 128, M / 128), 256>>>(
            (const __half*)pO, (const __half*)pWproj, M, DIM, DIM, e);
    }

    // 5) LN2(y1)
    ln_plain_kernel<<<NTOK / 4, 128>>>(y1, g2, be2, (__half*)pA2);

    // 6) FC1 + gelu
    {
        EpiGelu e{b_fc1, (__half*)pH};
        gemm_f16_kernel<EpiGelu><<<dim3(4 * DIM / 128, M / 128), 256>>>(
            (const __half*)pA2, (const __half*)pWfc1, M, 4 * DIM, DIM, e);
    }

    // 7) FC2 + residual -> y2
    {
        EpiY2 e{b_fc2, x2, y2};
        gemm_f16_kernel<EpiY2><<<dim3(DIM / 128, M / 128), 256>>>(
            (const __half*)pH, (const __half*)pWfc2, M, DIM, 4 * DIM, e);
    }
}

// round 6
// speedup vs baseline: 1.8889x; 1.8889x over previous
#include <cuda_runtime.h>
#include <cuda_fp16.h>
#include <cstdint>
#include <math.h>

// ---------------------------------------------------------------------------
// Problem constants
// ---------------------------------------------------------------------------
#define HIMG   56
#define WSZ    7
#define SSZ    3
#define DIM    384
#define HEADS  12
#define HDIM   32
#define NBATCH 16
#define NTOK   (NBATCH * HIMG * HIMG)     // 50176 rows
#define NWIMG  64                          // windows per image (8x8)
#define NWIN   (NBATCH * NWIMG)            // 1024 windows
#define NT     49                          // tokens per window

// ---------------------------------------------------------------------------
// Static scratch (no allocations allowed)
// ---------------------------------------------------------------------------
__device__ __half g_Awin[(size_t)NTOK * DIM];       // LN1+shift+partition, fp16
__device__ float  g_Q[(size_t)NTOK * DIM];          // [win][head][n][d] fp32 (pre-scaled)
__device__ float  g_K[(size_t)NTOK * DIM];
__device__ float  g_V[(size_t)NTOK * DIM];
__device__ __half g_O[(size_t)NTOK * DIM];          // attention out, row = win*49+n
__device__ __half g_A2[(size_t)NTOK * DIM];         // LN2(y1) fp16
__device__ __half g_Hm[(size_t)NTOK * 4 * DIM];     // gelu(fc1) fp16
__device__ __half g_Wqkv[DIM * 3 * DIM];
__device__ __half g_Wproj[DIM * DIM];
__device__ __half g_Wfc1[DIM * 4 * DIM];
__device__ __half g_Wfc2[4 * DIM * DIM];

// ---------------------------------------------------------------------------
// fp32 -> fp16 weight conversion
// ---------------------------------------------------------------------------
__global__ void f2h_kernel(const float* __restrict__ s, __half* __restrict__ d, int n) {
    int i = blockIdx.x * blockDim.x + threadIdx.x;
    if (i < n) d[i] = __float2half(s[i]);
}

// ---------------------------------------------------------------------------
// LayerNorm (+ optional shift/window gather). One warp per row.
// ---------------------------------------------------------------------------
__device__ __forceinline__ float warp_sum(float v) {
#pragma unroll
    for (int o = 16; o > 0; o >>= 1) v += __shfl_xor_sync(0xFFFFFFFFu, v, o);
    return v;
}

// gather variant: row r is a window-token; source token via +3 cyclic shift
__global__ void ln_gather_kernel(const float* __restrict__ x,
                                 const float* __restrict__ g,
                                 const float* __restrict__ b,
                                 __half* __restrict__ out) {
    int r    = blockIdx.x * 4 + (threadIdx.x >> 5);
    int lane = threadIdx.x & 31;
    int w = r / NT, n = r - w * NT;
    int bimg = w >> 6, wi = w & 63;
    int wr = wi >> 3, wc = wi & 7;
    int i = n / WSZ, j = n - i * WSZ;
    int hh = wr * WSZ + i + SSZ; if (hh >= HIMG) hh -= HIMG;
    int ww = wc * WSZ + j + SSZ; if (ww >= HIMG) ww -= HIMG;
    size_t t = (size_t)bimg * (HIMG * HIMG) + hh * HIMG + ww;

    const float* xp = x + t * DIM;
    float v[12];
    float s = 0.f;
#pragma unroll
    for (int k = 0; k < 12; k++) { v[k] = xp[lane + k * 32]; s += v[k]; }
    float mu = warp_sum(s) * (1.0f / DIM);
    float s2 = 0.f;
#pragma unroll
    for (int k = 0; k < 12; k++) { float d0 = v[k] - mu; s2 += d0 * d0; }
    float var = warp_sum(s2) * (1.0f / DIM);
    float rs = rsqrtf(var + 1e-5f);
    __half* op = out + (size_t)r * DIM;
#pragma unroll
    for (int k = 0; k < 12; k++) {
        int c = lane + k * 32;
        op[c] = __float2half((v[k] - mu) * rs * g[c] + b[c]);
    }
}

// plain variant (token order)
__global__ void ln_plain_kernel(const float* __restrict__ x,
                                const float* __restrict__ g,
                                const float* __restrict__ b,
                                __half* __restrict__ out) {
    int r    = blockIdx.x * 4 + (threadIdx.x >> 5);
    int lane = threadIdx.x & 31;
    const float* xp = x + (size_t)r * DIM;
    float v[12];
    float s = 0.f;
#pragma unroll
    for (int k = 0; k < 12; k++) { v[k] = xp[lane + k * 32]; s += v[k]; }
    float mu = warp_sum(s) * (1.0f / DIM);
    float s2 = 0.f;
#pragma unroll
    for (int k = 0; k < 12; k++) { float d0 = v[k] - mu; s2 += d0 * d0; }
    float var = warp_sum(s2) * (1.0f / DIM);
    float rs = rsqrtf(var + 1e-5f);
    __half* op = out + (size_t)r * DIM;
#pragma unroll
    for (int k = 0; k < 12; k++) {
        int c = lane + k * 32;
        op[c] = __float2half((v[k] - mu) * rs * g[c] + b[c]);
    }
}

// ---------------------------------------------------------------------------
// fp16 GEMM (mma.sync m16n8k16), 128x128x32 tiles, 8 warps, fused epilogue.
// 3-stage cp.async pipeline: loads for tile i+2 overlap compute of tile i.
// A: [M,K] row-major fp16, B: [K,N] row-major fp16, C consumed by Epi(r,c,v).
// M % 128 == 0, N % 128 == 0, K % 32 == 0, K/32 >= 2 (all hold here).
// ---------------------------------------------------------------------------
__device__ __forceinline__ unsigned smem_u32(const void* p) {
    return (unsigned)__cvta_generic_to_shared(p);
}

#define GEMM_STAGES 3

template <class Epi>
__global__ void __launch_bounds__(256)
gemm_f16_kernel(const __half* __restrict__ A, const __half* __restrict__ Bw,
                int M, int N, int K, Epi epi) {
    constexpr int BM = 128, BN = 128, BK = 32;
    // row strides padded: A row = 40 halves (80B, 16B-multiple), B row = 136 halves (272B)
    __shared__ __half Ash[GEMM_STAGES][BM][BK + 8];
    __shared__ __half Bsh[GEMM_STAGES][BK][BN + 8];

    const int tid = threadIdx.x;
    const int warp = tid >> 5, lane = tid & 31;
    const int wm = (warp >> 2) * 64;   // 2 warps along M
    const int wn = (warp & 3) * 32;    // 4 warps along N
    const int bm = blockIdx.y * BM;
    const int bn = blockIdx.x * BN;

    // per-thread load coordinates (4 x 16B cp.async per stage)
    const int ar0 = tid >> 2, ac = (tid & 3) * 8;          // A: rows tid/4, tid/4+64
    const int br0 = tid >> 4, bc = (tid & 15) * 8;         // B: rows tid/16, tid/16+16

    const __half* Abase = A + (size_t)bm * K;
    const __half* Bbase = Bw + bn;

    auto load_stage = [&](int st, int k0) {
        {
            unsigned d0 = smem_u32(&Ash[st][ar0][ac]);
            const void* s0 = Abase + (size_t)ar0 * K + k0 + ac;
            asm volatile("cp.async.cg.shared.global [%0], [%1], 16;\n" :: "r"(d0), "l"(s0));
            unsigned d1 = smem_u32(&Ash[st][ar0 + 64][ac]);
            const void* s1 = Abase + (size_t)(ar0 + 64) * K + k0 + ac;
            asm volatile("cp.async.cg.shared.global [%0], [%1], 16;\n" :: "r"(d1), "l"(s1));
        }
        {
            unsigned d0 = smem_u32(&Bsh[st][br0][bc]);
            const void* s0 = Bbase + (size_t)(k0 + br0) * N + bc;
            asm volatile("cp.async.cg.shared.global [%0], [%1], 16;\n" :: "r"(d0), "l"(s0));
            unsigned d1 = smem_u32(&Bsh[st][br0 + 16][bc]);
            const void* s1 = Bbase + (size_t)(k0 + br0 + 16) * N + bc;
            asm volatile("cp.async.cg.shared.global [%0], [%1], 16;\n" :: "r"(d1), "l"(s1));
        }
    };

    float acc[4][4][4];
#pragma unroll
    for (int a = 0; a < 4; a++)
#pragma unroll
        for (int b = 0; b < 4; b++)
#pragma unroll
            for (int c = 0; c < 4; c++) acc[a][b][c] = 0.f;

    const int ktiles = K / BK;

    // prologue: prefetch tiles 0 and 1
    load_stage(0, 0);
    asm volatile("cp.async.commit_group;\n");
    load_stage(1, BK);
    asm volatile("cp.async.commit_group;\n");

    for (int i = 0; i < ktiles; i++) {
        asm volatile("cp.async.wait_group 1;\n");   // tile i's group complete
        __syncthreads();                             // all warps see smem; buffer (i+2)%3 free

        const int s = i % GEMM_STAGES;

        // prefetch tile i+2 (overlaps with compute below)
        if (i + 2 < ktiles) load_stage((i + 2) % GEMM_STAGES, (i + 2) * BK);
        asm volatile("cp.async.commit_group;\n");

#pragma unroll
        for (int kk = 0; kk < BK; kk += 16) {
            uint32_t af[4][4], bf[4][2];
#pragma unroll
            for (int mi = 0; mi < 4; mi++) {
                unsigned addr = smem_u32(&Ash[s][wm + mi * 16 + (lane & 15)]
                                              [kk + (lane >> 4) * 8]);
                asm volatile(
                    "ldmatrix.sync.aligned.m8n8.x4.shared.b16 {%0,%1,%2,%3}, [%4];\n"
                    : "=r"(af[mi][0]), "=r"(af[mi][1]), "=r"(af[mi][2]), "=r"(af[mi][3])
                    : "r"(addr));
            }
#pragma unroll
            for (int ni = 0; ni < 4; ni++) {
                unsigned addr = smem_u32(&Bsh[s][kk + (lane & 15)][wn + ni * 8]);
                asm volatile(
                    "ldmatrix.sync.aligned.m8n8.x2.trans.shared.b16 {%0,%1}, [%2];\n"
                    : "=r"(bf[ni][0]), "=r"(bf[ni][1])
                    : "r"(addr));
            }
#pragma unroll
            for (int mi = 0; mi < 4; mi++)
#pragma unroll
                for (int ni = 0; ni < 4; ni++) {
                    asm volatile(
                        "mma.sync.aligned.m16n8k16.row.col.f32.f16.f16.f32 "
                        "{%0,%1,%2,%3}, {%4,%5,%6,%7}, {%8,%9}, {%0,%1,%2,%3};\n"
                        : "+f"(acc[mi][ni][0]), "+f"(acc[mi][ni][1]),
                          "+f"(acc[mi][ni][2]), "+f"(acc[mi][ni][3])
                        : "r"(af[mi][0]), "r"(af[mi][1]), "r"(af[mi][2]), "r"(af[mi][3]),
                          "r"(bf[ni][0]), "r"(bf[ni][1]));
                }
        }
        __syncthreads();   // compute done before next iteration's prefetch into (i+3)%3
    }

    // epilogue: element (r,c) per mma fragment layout
    const int r0 = bm + wm + (lane >> 2);
    const int c0 = bn + wn + (lane & 3) * 2;
#pragma unroll
    for (int mi = 0; mi < 4; mi++) {
#pragma unroll
        for (int ni = 0; ni < 4; ni++) {
            int rr = r0 + mi * 16;
            int cc = c0 + ni * 8;
            epi(rr,     cc,     acc[mi][ni][0]);
            epi(rr,     cc + 1, acc[mi][ni][1]);
            epi(rr + 8, cc,     acc[mi][ni][2]);
            epi(rr + 8, cc + 1, acc[mi][ni][3]);
        }
    }
}

// ---------------------------------------------------------------------------
// Epilogue functors
// ---------------------------------------------------------------------------
struct EpiQKV {
    const float* bias;
    float scale;
    float *Qo, *Ko, *Vo;
    __device__ __forceinline__ void operator()(int r, int c, float v) const {
        v += bias[c];
        int which = c / DIM;
        int rem = c - which * DIM;
        int h = rem >> 5, d = rem & 31;
        int w = r / NT, n = r - w * NT;
        size_t dst = (((size_t)(w * HEADS + h)) * NT + n) * HDIM + d;
        if (which == 0)      Qo[dst] = v * scale;
        else if (which == 1) Ko[dst] = v;
        else                 Vo[dst] = v;
    }
};

struct EpiProj {  // + bias, window-reverse + unshift scatter, + x1 residual -> y1
    const float* bias;
    const float* x1;
    float* y1;
    __device__ __forceinline__ void operator()(int r, int c, float v) const {
        int w = r / NT, n = r - w * NT;
        int bimg = w >> 6, wi = w & 63;
        int wr = wi >> 3, wc = wi & 7;
        int i = n / WSZ, j = n - i * WSZ;
        int hh = wr * WSZ + i + SSZ; if (hh >= HIMG) hh -= HIMG;
        int ww = wc * WSZ + j + SSZ; if (ww >= HIMG) ww -= HIMG;
        size_t t = (size_t)bimg * (HIMG * HIMG) + hh * HIMG + ww;
        size_t o = t * DIM + c;
        y1[o] = x1[o] + v + bias[c];
    }
};

struct EpiGelu {  // + bias, exact gelu, fp16 store
    const float* bias;
    __half* Ho;
    __device__ __forceinline__ void operator()(int r, int c, float v) const {
        v += bias[c];
        float gl = 0.5f * v * (1.0f + erff(v * 0.70710678118654752f));
        Ho[(size_t)r * (4 * DIM) + c] = __float2half(gl);
    }
};

struct EpiY2 {  // + bias + x2 residual -> y2
    const float* bias;
    const float* x2;
    float* y2;
    __device__ __forceinline__ void operator()(int r, int c, float v) const {
        size_t o = (size_t)r * DIM + c;
        y2[o] = x2[o] + v + bias[c];
    }
};

// ---------------------------------------------------------------------------
// Windowed attention: one block per (window, head). fp32 softmax.
// Q pre-scaled by 1/sqrt(d). Output fp16 in proj-GEMM A layout.
// ---------------------------------------------------------------------------
__global__ void __launch_bounds__(64)
attn_kernel(const float* __restrict__ Q, const float* __restrict__ K,
            const float* __restrict__ V, const float* __restrict__ rpb,
            const float* __restrict__ mask, __half* __restrict__ O) {
    int wh = blockIdx.x;
    int w = wh / HEADS, h = wh - w * HEADS;
    int wi = w & 63;   // window index within image (for mask)

    __shared__ float ks[NT][HDIM];
    __shared__ float vs[NT][HDIM];

    const size_t base = (size_t)wh * NT * HDIM;
    for (int idx = threadIdx.x; idx < NT * HDIM; idx += 64) {
        ks[idx >> 5][idx & 31] = K[base + idx];
        vs[idx >> 5][idx & 31] = V[base + idx];
    }
    __syncthreads();

    int n = threadIdx.x;
    if (n < NT) {
        float q[HDIM];
        const float* qp = Q + base + (size_t)n * HDIM;
#pragma unroll
        for (int d = 0; d < HDIM; d++) q[d] = qp[d];

        int i1 = n / WSZ, j1 = n - i1 * WSZ;
        const float* mrow = mask + ((size_t)wi * NT + n) * NT;

        float s[NT];
        float mx = -1e30f;
#pragma unroll
        for (int m = 0; m < NT; m++) {
            float dot = 0.f;
#pragma unroll
            for (int d = 0; d < HDIM; d++) dot += q[d] * ks[m][d];
            int i2 = m / WSZ, j2 = m - i2 * WSZ;
            int ridx = (i1 - i2 + WSZ - 1) * (2 * WSZ - 1) + (j1 - j2 + WSZ - 1);
            float val = dot + rpb[ridx * HEADS + h] + mrow[m];
            s[m] = val;
            mx = fmaxf(mx, val);
        }
        float sum = 0.f;
#pragma unroll
        for (int m = 0; m < NT; m++) {
            float p = expf(s[m] - mx);
            s[m] = p;
            sum += p;
        }
        float inv = 1.0f / sum;

        float o[HDIM];
#pragma unroll
        for (int d = 0; d < HDIM; d++) o[d] = 0.f;
#pragma unroll
        for (int m = 0; m < NT; m++) {
            float p = s[m];
#pragma unroll
            for (int d = 0; d < HDIM; d++) o[d] += p * vs[m][d];
        }
        __half* op = O + ((size_t)(w * NT + n)) * DIM + h * HDIM;
#pragma unroll
        for (int d = 0; d < HDIM; d++) op[d] = __float2half(o[d] * inv);
    }
}

// ---------------------------------------------------------------------------
// Launch
// ---------------------------------------------------------------------------
extern "C" void kernel_launch(void* const* d_in, const int* in_sizes, int n_in,
                              void* d_out, int out_size) {
    const float* x1     = (const float*)d_in[0];
    const float* x2     = (const float*)d_in[1];
    const float* amask  = (const float*)d_in[2];
    const float* g1     = (const float*)d_in[3];
    const float* be1    = (const float*)d_in[4];
    const float* w_qkv  = (const float*)d_in[5];
    const float* b_qkv  = (const float*)d_in[6];
    const float* rpb    = (const float*)d_in[7];
    const float* w_proj = (const float*)d_in[8];
    const float* b_proj = (const float*)d_in[9];
    const float* g2     = (const float*)d_in[10];
    const float* be2    = (const float*)d_in[11];
    const float* w_fc1  = (const float*)d_in[12];
    const float* b_fc1  = (const float*)d_in[13];
    const float* w_fc2  = (const float*)d_in[14];
    const float* b_fc2  = (const float*)d_in[15];

    float* out = (float*)d_out;
    float* y1 = out;
    float* y2 = out + (size_t)NTOK * DIM;

    void *pAwin, *pQ, *pK, *pV, *pO, *pA2, *pH;
    void *pWqkv, *pWproj, *pWfc1, *pWfc2;
    cudaGetSymbolAddress(&pAwin, g_Awin);
    cudaGetSymbolAddress(&pQ, g_Q);
    cudaGetSymbolAddress(&pK, g_K);
    cudaGetSymbolAddress(&pV, g_V);
    cudaGetSymbolAddress(&pO, g_O);
    cudaGetSymbolAddress(&pA2, g_A2);
    cudaGetSymbolAddress(&pH, g_Hm);
    cudaGetSymbolAddress(&pWqkv, g_Wqkv);
    cudaGetSymbolAddress(&pWproj, g_Wproj);
    cudaGetSymbolAddress(&pWfc1, g_Wfc1);
    cudaGetSymbolAddress(&pWfc2, g_Wfc2);

    // weights -> fp16
    f2h_kernel<<<(DIM * 3 * DIM + 255) / 256, 256>>>(w_qkv, (__half*)pWqkv, DIM * 3 * DIM);
    f2h_kernel<<<(DIM * DIM + 255) / 256, 256>>>(w_proj, (__half*)pWproj, DIM * DIM);
    f2h_kernel<<<(DIM * 4 * DIM + 255) / 256, 256>>>(w_fc1, (__half*)pWfc1, DIM * 4 * DIM);
    f2h_kernel<<<(4 * DIM * DIM + 255) / 256, 256>>>(w_fc2, (__half*)pWfc2, 4 * DIM * DIM);

    const int M = NTOK;

    // 1) LN1 + shift + window partition
    ln_gather_kernel<<<NTOK / 4, 128>>>(x2, g1, be1, (__half*)pAwin);

    // 2) QKV GEMM + scatter
    {
        EpiQKV e{b_qkv, 0.17677669529663687f, (float*)pQ, (float*)pK, (float*)pV};
        gemm_f16_kernel<EpiQKV><<<dim3(3 * DIM / 128, M / 128), 256>>>(
            (const __half*)pAwin, (const __half*)pWqkv, M, 3 * DIM, DIM, e);
    }

    // 3) attention
    attn_kernel<<<NWIN * HEADS, 64>>>((const float*)pQ, (const float*)pK,
                                      (const float*)pV, rpb, amask, (__half*)pO);

    // 4) proj + window reverse + residual -> y1
    {
        EpiProj e{b_proj, x1, y1};
        gemm_f16_kernel<EpiProj><<<dim3(DIM / 128, M / 128), 256>>>(
            (const __half*)pO, (const __half*)pWproj, M, DIM, DIM, e);
    }

    // 5) LN2(y1)
    ln_plain_kernel<<<NTOK / 4, 128>>>(y1, g2, be2, (__half*)pA2);

    // 6) FC1 + gelu
    {
        EpiGelu e{b_fc1, (__half*)pH};
        gemm_f16_kernel<EpiGelu><<<dim3(4 * DIM / 128, M / 128), 256>>>(
            (const __half*)pA2, (const __half*)pWfc1, M, 4 * DIM, DIM, e);
    }

    // 7) FC2 + residual -> y2
    {
        EpiY2 e{b_fc2, x2, y2};
        gemm_f16_kernel<EpiY2><<<dim3(DIM / 128, M / 128), 256>>>(
            (const __half*)pH, (const __half*)pWfc2, M, DIM, 4 * DIM, e);
    }
}